// round 9
// baseline (speedup 1.0000x reference)
#include <cuda_runtime.h>
#include <math.h>

#define BB 64
#define TT 256
#define FF 512
#define UU 1024
#define NB 128   // persistent CTAs (<= SM count -> all co-resident)

// ---------------------------------------------------------------------------
// Device-global scratch (no allocations allowed anywhere)
// ---------------------------------------------------------------------------
__device__ float g_XP[BB * TT * UU];        // x @ kernel_x precomputed (67 MB)
__device__ float g_zero[BB * UU];           // never written -> stays zero
__device__ float g_xx[BB * UU];
__device__ float g_c[BB * UU];              // LN2(longterm) carry
__device__ float g_st1[BB * UU];            // LN1(shortterm)
__device__ float g_att[BB * UU];
__device__ float g_xxp[16][BB * UU];        // split-K partials
__device__ float g_fip[8][BB * 2048];
__device__ float g_qkvp[16][BB * 3072];
__device__ float g_outp[16][BB * UU];
__device__ float g_Wfi[UU * 2048];          // [W_f | W_i]
__device__ float g_Wqkv[UU * 3072];         // [W_q | W_k | W_v]

// grid barrier state (cumulative across launches)
__device__ unsigned g_arrive;
__device__ volatile unsigned g_release;

// ---------------------------------------------------------------------------
// Software grid barrier (all NB CTAs resident). Cumulative counter: no reset,
// no sense flag; state carries across kernel launches (phase seeded from
// g_release at kernel entry).
// ---------------------------------------------------------------------------
__device__ __forceinline__ void gsync(unsigned &phase)
{
    __syncthreads();
    phase += 1u;
    if (threadIdx.x == 0) {
        __threadfence();
        unsigned prev = atomicAdd(&g_arrive, 1u);
        if (prev == phase * (unsigned)NB - 1u) {
            __threadfence();
            g_release = phase;
        } else {
            while (g_release < phase) { }
            __threadfence();
        }
    }
    __syncthreads();
}

// ---------------------------------------------------------------------------
// 64-row x 128-col tile GEMM over K slice [k0, k0+ksz), fp32x2 packed FMA.
// 256 threads: 16x16 thread grid, 4 rows x 8 cols per thread.
// Writes the tile into C (a split-K partial buffer), row stride ldc.
// ---------------------------------------------------------------------------
#define FMA2(acc, s, w) asm("fma.rn.f32x2 %0,%1,%2,%0;" : "+l"(acc) : "l"(s), "l"(w))

__device__ __noinline__ void gemm_tile(
    const float* __restrict__ A, int lda,
    const float* __restrict__ W, int ldw,
    float* __restrict__ C, int ldc,
    int colbase, int k0, int ksz)
{
    __shared__ __align__(16) float sA[32 * 68];    // [kk][row], stride 68 (16B-aligned)
    __shared__ __align__(16) float sW[32 * 128];   // [kk][col]

    const int tid = threadIdx.x;
    const int tx = tid & 15;        // col group (8 cols)
    const int ty = tid >> 4;        // row group (4 rows)

    unsigned long long c00=0,c01=0,c02=0,c03=0;
    unsigned long long c10=0,c11=0,c12=0,c13=0;
    unsigned long long c20=0,c21=0,c22=0,c23=0;
    unsigned long long c30=0,c31=0,c32=0,c33=0;

    for (int kt = 0; kt < ksz; kt += 32) {
        const int kg = k0 + kt;
        __syncthreads();
        // A: 64 rows x 32 k -> transposed into sA[kk][row]
#pragma unroll
        for (int i = 0; i < 2; i++) {
            int idx = tid + i * 256;              // 0..511
            int r  = idx >> 3;                    // 0..63
            int k4 = (idx & 7) << 2;              // 0,4,..,28
            float4 a = *(const float4*)(A + (size_t)r * lda + kg + k4);
            sA[(k4 + 0) * 68 + r] = a.x;
            sA[(k4 + 1) * 68 + r] = a.y;
            sA[(k4 + 2) * 68 + r] = a.z;
            sA[(k4 + 3) * 68 + r] = a.w;
        }
        // W: 32 k x 128 cols, direct float4 copy
#pragma unroll
        for (int i = 0; i < 4; i++) {
            int idx = tid + i * 256;              // 0..1023
            int kk = idx >> 5;                    // 0..31
            int c4 = (idx & 31) << 2;             // 0..124
            *(float4*)(sW + kk * 128 + c4) =
                *(const float4*)(W + (size_t)(kg + kk) * ldw + colbase + c4);
        }
        __syncthreads();
#pragma unroll
        for (int kk = 0; kk < 32; kk++) {
            float4 av = *(const float4*)(sA + kk * 68 + ty * 4);
            ulonglong2 w0 = *(const ulonglong2*)(sW + kk * 128 + tx * 8);
            ulonglong2 w1 = *(const ulonglong2*)(sW + kk * 128 + tx * 8 + 4);
            unsigned long long s0, s1, s2, s3;
            asm("mov.b64 %0,{%1,%1};" : "=l"(s0) : "f"(av.x));
            asm("mov.b64 %0,{%1,%1};" : "=l"(s1) : "f"(av.y));
            asm("mov.b64 %0,{%1,%1};" : "=l"(s2) : "f"(av.z));
            asm("mov.b64 %0,{%1,%1};" : "=l"(s3) : "f"(av.w));
            FMA2(c00, s0, w0.x); FMA2(c01, s0, w0.y); FMA2(c02, s0, w1.x); FMA2(c03, s0, w1.y);
            FMA2(c10, s1, w0.x); FMA2(c11, s1, w0.y); FMA2(c12, s1, w1.x); FMA2(c13, s1, w1.y);
            FMA2(c20, s2, w0.x); FMA2(c21, s2, w0.y); FMA2(c22, s2, w1.x); FMA2(c23, s2, w1.y);
            FMA2(c30, s3, w0.x); FMA2(c31, s3, w0.y); FMA2(c32, s3, w1.x); FMA2(c33, s3, w1.y);
        }
    }

    // store 4 rows x 8 cols
    unsigned long long rr[4][4] = {{c00,c01,c02,c03},{c10,c11,c12,c13},
                                   {c20,c21,c22,c23},{c30,c31,c32,c33}};
#pragma unroll
    for (int r = 0; r < 4; r++) {
        float o0,o1,o2,o3,o4,o5,o6,o7;
        asm("mov.b64 {%0,%1},%2;" : "=f"(o0), "=f"(o1) : "l"(rr[r][0]));
        asm("mov.b64 {%0,%1},%2;" : "=f"(o2), "=f"(o3) : "l"(rr[r][1]));
        asm("mov.b64 {%0,%1},%2;" : "=f"(o4), "=f"(o5) : "l"(rr[r][2]));
        asm("mov.b64 {%0,%1},%2;" : "=f"(o6), "=f"(o7) : "l"(rr[r][3]));
        size_t base = (size_t)(ty * 4 + r) * ldc + colbase + tx * 8;
        *(float4*)(C + base)     = make_float4(o0, o1, o2, o3);
        *(float4*)(C + base + 4) = make_float4(o4, o5, o6, o7);
    }
}

// ---------------------------------------------------------------------------
// Fused epilogue: reduce f/i partials, gates, longterm, swish chain, both
// LayerNorms. One CTA per batch row b (256 threads, 4 elems each).
// ---------------------------------------------------------------------------
__device__ __noinline__ void fi_epi(int b,
    const float* __restrict__ g1, const float* __restrict__ b1,
    const float* __restrict__ g2, const float* __restrict__ b2)
{
    __shared__ float red[4][8];
    const int t = threadIdx.x;
    float st[4], lt[4];
    float s1 = 0.f, s2 = 0.f, s3 = 0.f, s4 = 0.f;

#pragma unroll
    for (int i = 0; i < 4; i++) {
        int j = t + i * 256;
        int base = b * 2048 + j;
        float fa = 0.f, ia = 0.f;
#pragma unroll
        for (int sp = 0; sp < 8; sp++) {
            fa += g_fip[sp][base];
            ia += g_fip[sp][base + 1024];
        }
        float xxv = g_xx[b * UU + j];
        float f    = 1.0f / (1.0f + __expf(-fa));
        float ii   = 1.0f / (1.0f + __expf(-ia));
        float cand = tanhf(xxv);
        float ltv  = f * g_c[b * UU + j] + ii * cand;
        float sxx  = xxv / (1.0f + __expf(-xxv));          // swish(xx)
        float z    = ltv + sxx;
        float stv  = z / (1.0f + __expf(-z));              // swish(lt + swish(xx))
        st[i] = stv; lt[i] = ltv;
        s1 += stv; s2 += stv * stv; s3 += ltv; s4 += ltv * ltv;
    }

    const int lane = t & 31, wid = t >> 5;
#pragma unroll
    for (int o = 16; o > 0; o >>= 1) {
        s1 += __shfl_down_sync(0xffffffffu, s1, o);
        s2 += __shfl_down_sync(0xffffffffu, s2, o);
        s3 += __shfl_down_sync(0xffffffffu, s3, o);
        s4 += __shfl_down_sync(0xffffffffu, s4, o);
    }
    if (lane == 0) { red[0][wid] = s1; red[1][wid] = s2; red[2][wid] = s3; red[3][wid] = s4; }
    __syncthreads();
    float S1 = 0.f, S2 = 0.f, S3 = 0.f, S4 = 0.f;
#pragma unroll
    for (int w = 0; w < 8; w++) { S1 += red[0][w]; S2 += red[1][w]; S3 += red[2][w]; S4 += red[3][w]; }
    const float inv = 1.0f / (float)UU;
    float m1 = S1 * inv, v1 = S2 * inv - m1 * m1;
    float m2 = S3 * inv, v2 = S4 * inv - m2 * m2;
    float r1 = rsqrtf(v1 + 1e-3f);
    float r2 = rsqrtf(v2 + 1e-3f);

#pragma unroll
    for (int i = 0; i < 4; i++) {
        int j = t + i * 256;
        g_st1[b * UU + j] = (st[i] - m1) * r1 * g1[j] + b1[j];
        g_c[b * UU + j]   = (lt[i] - m2) * r2 * g2[j] + b2[j];
    }
}

// ---------------------------------------------------------------------------
// Mini 8-head attention (heads are the "sequence"). One CTA per batch row.
// ---------------------------------------------------------------------------
__device__ __noinline__ void attn(int b)
{
    __shared__ float q[1024], k[1024], v[1024], sc[64];
    const int t = threadIdx.x;

    for (int j = t; j < 3072; j += 256) {
        int base = b * 3072 + j;
        float s = 0.f;
#pragma unroll
        for (int sp = 0; sp < 16; sp++) s += g_qkvp[sp][base];
        if (j < 1024)       q[j] = s;
        else if (j < 2048)  k[j - 1024] = s;
        else                v[j - 2048] = s;
    }
    __syncthreads();

    if (t < 64) {
        int h = t >> 3, g = t & 7;
        float s = 0.f;
#pragma unroll 8
        for (int d = 0; d < 128; d++) s += q[h * 128 + d] * k[g * 128 + d];
        sc[t] = s * 0.08838834764831845f;   // 1/sqrt(128)
    }
    __syncthreads();

    if (t < 8) {
        float mx = -1e30f;
#pragma unroll
        for (int g = 0; g < 8; g++) mx = fmaxf(mx, sc[t * 8 + g]);
        float e[8], sum = 0.f;
#pragma unroll
        for (int g = 0; g < 8; g++) { e[g] = __expf(sc[t * 8 + g] - mx); sum += e[g]; }
        float is = 1.0f / sum;
#pragma unroll
        for (int g = 0; g < 8; g++) sc[t * 8 + g] = e[g] * is;
    }
    __syncthreads();

    for (int j = t; j < 1024; j += 256) {
        int h = j >> 7, d = j & 127;
        float a = 0.f;
#pragma unroll
        for (int g = 0; g < 8; g++) a += sc[h * 8 + g] * v[g * 128 + d];
        g_att[b * UU + j] = a;
    }
}

// ---------------------------------------------------------------------------
// The single persistent kernel: everything lives here.
// ---------------------------------------------------------------------------
__global__ void __launch_bounds__(256, 1) persist(
    const float* __restrict__ x,  const float* __restrict__ kx, const float* __restrict__ kh,
    const float* __restrict__ Wq, const float* __restrict__ Wk, const float* __restrict__ Wv,
    const float* __restrict__ Wo, const float* __restrict__ Wf, const float* __restrict__ Wi,
    const float* __restrict__ g1, const float* __restrict__ b1,
    const float* __restrict__ g2, const float* __restrict__ b2,
    float* __restrict__ y)
{
    unsigned phase = g_release;                       // carries across launches
    const int tid = threadIdx.x;
    const int gt  = blockIdx.x * 256 + tid;           // 0..32767

    // phase 0: pack fused weights, zero carry
    for (int i = gt; i < UU * 2048; i += NB * 256) {
        int kk = i >> 11, j = i & 2047;
        g_Wfi[i] = (j < 1024) ? Wf[(kk << 10) + j] : Wi[(kk << 10) + j - 1024];
    }
    for (int i = gt; i < UU * 3072; i += NB * 256) {
        int kk = i / 3072, j = i - kk * 3072;
        float vv = (j < 1024) ? Wq[kk * 1024 + j]
                 : (j < 2048) ? Wk[kk * 1024 + j - 1024]
                              : Wv[kk * 1024 + j - 2048];
        g_Wqkv[i] = vv;
    }
    for (int i = gt; i < BB * UU; i += NB * 256) g_c[i] = 0.f;
    gsync(phase);

    // XP = x @ kernel_x  (16384 x 512 @ 512 x 1024): 256 rowtiles x 8 coltiles
    for (int u = blockIdx.x; u < 2048; u += NB) {
        int rt = u >> 3, ct = u & 7;
        gemm_tile(x + (size_t)rt * 64 * FF, FF, kx, UU,
                  g_XP + (size_t)rt * 64 * UU, UU, ct * 128, 0, FF);
    }
    gsync(phase);

    for (int t = 0; t < TT; t++) {
        const float* h = (t == 0) ? g_zero : (y + (size_t)(t - 1) * UU);
        const int ldh  = (t == 0) ? UU : (TT * UU);

        // ph1: xx partials = h @ kernel_h  (8 coltiles x 16 ksplits of 64)
        for (int u = blockIdx.x; u < 128; u += NB) {
            int ks = u >> 3, ct = u & 7;
            gemm_tile(h, ldh, kh, UU, g_xxp[ks], UU, ct * 128, ks * 64, 64);
        }
        gsync(phase);

        // ph2: xx = XP[:,t,:] + sum partials
        for (int i = gt; i < BB * UU; i += NB * 256) {
            int b = i >> 10, uu = i & 1023;
            float s = g_XP[(size_t)((b << 8) + t) * UU + uu];
#pragma unroll
            for (int sp = 0; sp < 16; sp++) s += g_xxp[sp][i];
            g_xx[i] = s;
        }
        gsync(phase);

        // ph3: [f|i] partials = xx @ Wfi  (16 coltiles x 8 ksplits of 128)
        for (int u = blockIdx.x; u < 128; u += NB) {
            int ks = u >> 4, ct = u & 15;
            gemm_tile(g_xx, UU, g_Wfi, 2048, g_fip[ks], 2048, ct * 128, ks * 128, 128);
        }
        gsync(phase);

        // ph4: gates + swish + both LayerNorms
        if (blockIdx.x < 64) fi_epi(blockIdx.x, g1, b1, g2, b2);
        gsync(phase);

        // ph5: [q|k|v] partials = st1 @ Wqkv  (24 coltiles x 16 ksplits of 64)
        for (int u = blockIdx.x; u < 384; u += NB) {
            int ks = u / 24, ct = u - ks * 24;
            gemm_tile(g_st1, UU, g_Wqkv, 3072, g_qkvp[ks], 3072, ct * 128, ks * 64, 64);
        }
        gsync(phase);

        // ph6: attention
        if (blockIdx.x < 64) attn(blockIdx.x);
        gsync(phase);

        // ph7: out partials = attended @ W_o  (8 coltiles x 16 ksplits of 64)
        for (int u = blockIdx.x; u < 128; u += NB) {
            int ks = u >> 3, ct = u & 7;
            gemm_tile(g_att, UU, Wo, UU, g_outp[ks], UU, ct * 128, ks * 64, 64);
        }
        gsync(phase);

        // ph8: y[:,t,:] = st1 + sum out partials  (= h for t+1)
        for (int i = gt; i < BB * UU; i += NB * 256) {
            int b = i >> 10, uu = i & 1023;
            float s = g_st1[i];
#pragma unroll
            for (int sp = 0; sp < 16; sp++) s += g_outp[sp][i];
            y[(size_t)b * (TT * UU) + (size_t)t * UU + uu] = s;
        }
        gsync(phase);
    }
}

// ---------------------------------------------------------------------------
// Host: ONE launch -> graph has a single node.
// ---------------------------------------------------------------------------
extern "C" void kernel_launch(void* const* d_in, const int* in_sizes, int n_in,
                              void* d_out, int out_size)
{
    (void)in_sizes; (void)n_in; (void)out_size;
    persist<<<NB, 256>>>(
        (const float*)d_in[0],  (const float*)d_in[1],  (const float*)d_in[2],
        (const float*)d_in[3],  (const float*)d_in[4],  (const float*)d_in[5],
        (const float*)d_in[6],  (const float*)d_in[7],  (const float*)d_in[8],
        (const float*)d_in[9],  (const float*)d_in[10],
        (const float*)d_in[11], (const float*)d_in[12],
        (float*)d_out);
}

// round 10
// speedup vs baseline: 1.2390x; 1.2390x over previous
#include <cuda_runtime.h>
#include <math.h>

#define BB 64
#define TT 256
#define FF 512
#define UU 1024
#define NB 128   // persistent CTAs (1/SM, all co-resident)

// ---------------------------------------------------------------------------
// Device-global scratch (no allocations allowed anywhere)
// ---------------------------------------------------------------------------
__device__ float g_XP[BB * TT * UU];        // x @ kernel_x precomputed
__device__ float g_zero[BB * UU];           // never written -> stays zero
__device__ float g_xx[BB * UU];
__device__ float g_c[BB * UU];              // LN2(longterm) carry
__device__ float g_st1[BB * UU];            // LN1(shortterm)
__device__ float g_att[BB * UU];
__device__ float g_xxp[32][BB * UU];        // split-K partials
__device__ float g_fip[16][BB * 2048];
__device__ float g_qkvp[32][BB * 3072];
__device__ float g_outp[32][BB * UU];
__device__ float g_Wfi[UU * 2048];          // [W_f | W_i]
__device__ float g_Wqkv[UU * 3072];         // [W_q | W_k | W_v]

// grid barrier state (cumulative across launches)
__device__ unsigned g_arrive;
__device__ volatile unsigned g_release;

__device__ __forceinline__ void gsync(unsigned &phase)
{
    __syncthreads();
    phase += 1u;
    if (threadIdx.x == 0) {
        __threadfence();
        unsigned prev = atomicAdd(&g_arrive, 1u);
        if (prev == phase * (unsigned)NB - 1u) {
            __threadfence();
            g_release = phase;
        } else {
            while (g_release < phase) { }
            __threadfence();
        }
    }
    __syncthreads();
}

// ---------------------------------------------------------------------------
// 64-row x 256-col tile GEMM over K slice [k0, k0+ksz).
// 256 threads: ty = tid>>5 (8 row-octets), tx = tid&31 (col groups).
// Each thread: 8 rows x (cols tx*4..+3 and 128+tx*4..+3) -> 8x8 microtile,
// 32 fma.rn.f32x2 per k. A reads are warp-broadcast; W reads are contiguous
// 512B per LDS.128 -> conflict-free.
// ---------------------------------------------------------------------------
#define FMA2(acc, s, w) asm("fma.rn.f32x2 %0,%1,%2,%0;" : "+l"(acc) : "l"(s), "l"(w))
#define DUP(d, f)       asm("mov.b64 %0,{%1,%1};" : "=l"(d) : "f"(f))
#define UNPK(lo, hi, v) asm("mov.b64 {%0,%1},%2;" : "=f"(lo), "=f"(hi) : "l"(v))

__device__ __noinline__ void gemm_tile(
    const float* __restrict__ A, int lda,
    const float* __restrict__ W, int ldw,
    float* __restrict__ C, int ldc,
    int colbase, int k0, int ksz)
{
    __shared__ __align__(16) float sA[32 * 68];    // [kk][row]
    __shared__ __align__(16) float sW[32 * 256];   // [kk][col]

    const int tid = threadIdx.x;
    const int tx = tid & 31;
    const int ty = tid >> 5;

    unsigned long long acc[8][4];
#pragma unroll
    for (int r = 0; r < 8; r++) { acc[r][0] = acc[r][1] = acc[r][2] = acc[r][3] = 0ull; }

    for (int kt = 0; kt < ksz; kt += 32) {
        const int kg = k0 + kt;
        __syncthreads();
        // A: 64 rows x 32 k -> transposed into sA[kk][row] (512 float4 loads)
#pragma unroll
        for (int i = 0; i < 2; i++) {
            int idx = tid + i * 256;
            int r = idx >> 3, k4 = (idx & 7) << 2;
            float4 a = *(const float4*)(A + (size_t)r * lda + kg + k4);
            sA[(k4 + 0) * 68 + r] = a.x;
            sA[(k4 + 1) * 68 + r] = a.y;
            sA[(k4 + 2) * 68 + r] = a.z;
            sA[(k4 + 3) * 68 + r] = a.w;
        }
        // W: 32 k x 256 cols (2048 float4, 8 per thread, fully coalesced)
#pragma unroll
        for (int i = 0; i < 8; i++) {
            int idx = tid + i * 256;
            int kk = idx >> 6, c4 = (idx & 63) << 2;
            *(float4*)(sW + kk * 256 + c4) =
                *(const float4*)(W + (size_t)(kg + kk) * ldw + colbase + c4);
        }
        __syncthreads();
#pragma unroll 8
        for (int kk = 0; kk < 32; kk++) {
            float4 a0 = *(const float4*)(sA + kk * 68 + ty * 8);
            float4 a1 = *(const float4*)(sA + kk * 68 + ty * 8 + 4);
            ulonglong2 w0 = *(const ulonglong2*)(sW + kk * 256 + tx * 4);
            ulonglong2 w1 = *(const ulonglong2*)(sW + kk * 256 + 128 + tx * 4);
            unsigned long long s;
            DUP(s, a0.x); FMA2(acc[0][0], s, w0.x); FMA2(acc[0][1], s, w0.y); FMA2(acc[0][2], s, w1.x); FMA2(acc[0][3], s, w1.y);
            DUP(s, a0.y); FMA2(acc[1][0], s, w0.x); FMA2(acc[1][1], s, w0.y); FMA2(acc[1][2], s, w1.x); FMA2(acc[1][3], s, w1.y);
            DUP(s, a0.z); FMA2(acc[2][0], s, w0.x); FMA2(acc[2][1], s, w0.y); FMA2(acc[2][2], s, w1.x); FMA2(acc[2][3], s, w1.y);
            DUP(s, a0.w); FMA2(acc[3][0], s, w0.x); FMA2(acc[3][1], s, w0.y); FMA2(acc[3][2], s, w1.x); FMA2(acc[3][3], s, w1.y);
            DUP(s, a1.x); FMA2(acc[4][0], s, w0.x); FMA2(acc[4][1], s, w0.y); FMA2(acc[4][2], s, w1.x); FMA2(acc[4][3], s, w1.y);
            DUP(s, a1.y); FMA2(acc[5][0], s, w0.x); FMA2(acc[5][1], s, w0.y); FMA2(acc[5][2], s, w1.x); FMA2(acc[5][3], s, w1.y);
            DUP(s, a1.z); FMA2(acc[6][0], s, w0.x); FMA2(acc[6][1], s, w0.y); FMA2(acc[6][2], s, w1.x); FMA2(acc[6][3], s, w1.y);
            DUP(s, a1.w); FMA2(acc[7][0], s, w0.x); FMA2(acc[7][1], s, w0.y); FMA2(acc[7][2], s, w1.x); FMA2(acc[7][3], s, w1.y);
        }
    }

#pragma unroll
    for (int r = 0; r < 8; r++) {
        float f0, f1, f2, f3, f4, f5, f6, f7;
        UNPK(f0, f1, acc[r][0]); UNPK(f2, f3, acc[r][1]);
        UNPK(f4, f5, acc[r][2]); UNPK(f6, f7, acc[r][3]);
        size_t base = (size_t)(ty * 8 + r) * ldc + colbase + tx * 4;
        *(float4*)(C + base)       = make_float4(f0, f1, f2, f3);
        *(float4*)(C + base + 128) = make_float4(f4, f5, f6, f7);
    }
}

// ---------------------------------------------------------------------------
// Fused epilogue: reduce f/i partials (16), gates, longterm, swish chain,
// both LayerNorms. One CTA per batch row b.
// ---------------------------------------------------------------------------
__device__ __noinline__ void fi_epi(int b,
    const float* __restrict__ g1, const float* __restrict__ b1,
    const float* __restrict__ g2, const float* __restrict__ b2)
{
    __shared__ float red[4][8];
    const int t = threadIdx.x;
    float st[4], lt[4];
    float s1 = 0.f, s2 = 0.f, s3 = 0.f, s4 = 0.f;

#pragma unroll
    for (int i = 0; i < 4; i++) {
        int j = t + i * 256;
        int base = b * 2048 + j;
        float fa = 0.f, ia = 0.f;
#pragma unroll
        for (int sp = 0; sp < 16; sp++) {
            fa += g_fip[sp][base];
            ia += g_fip[sp][base + 1024];
        }
        float xxv = g_xx[b * UU + j];
        float f    = 1.0f / (1.0f + expf(-fa));
        float ii   = 1.0f / (1.0f + expf(-ia));
        float cand = tanhf(xxv);
        float ltv  = f * g_c[b * UU + j] + ii * cand;
        float sxx  = xxv / (1.0f + expf(-xxv));            // swish(xx)
        float z    = ltv + sxx;
        float stv  = z / (1.0f + expf(-z));                // swish(lt + swish(xx))
        st[i] = stv; lt[i] = ltv;
        s1 += stv; s2 += stv * stv; s3 += ltv; s4 += ltv * ltv;
    }

    const int lane = t & 31, wid = t >> 5;
#pragma unroll
    for (int o = 16; o > 0; o >>= 1) {
        s1 += __shfl_down_sync(0xffffffffu, s1, o);
        s2 += __shfl_down_sync(0xffffffffu, s2, o);
        s3 += __shfl_down_sync(0xffffffffu, s3, o);
        s4 += __shfl_down_sync(0xffffffffu, s4, o);
    }
    if (lane == 0) { red[0][wid] = s1; red[1][wid] = s2; red[2][wid] = s3; red[3][wid] = s4; }
    __syncthreads();
    float S1 = 0.f, S2 = 0.f, S3 = 0.f, S4 = 0.f;
#pragma unroll
    for (int w = 0; w < 8; w++) { S1 += red[0][w]; S2 += red[1][w]; S3 += red[2][w]; S4 += red[3][w]; }
    const float inv = 1.0f / (float)UU;
    float m1 = S1 * inv, v1 = S2 * inv - m1 * m1;
    float m2 = S3 * inv, v2 = S4 * inv - m2 * m2;
    float r1 = rsqrtf(v1 + 1e-3f);
    float r2 = rsqrtf(v2 + 1e-3f);

#pragma unroll
    for (int i = 0; i < 4; i++) {
        int j = t + i * 256;
        g_st1[b * UU + j] = (st[i] - m1) * r1 * g1[j] + b1[j];
        g_c[b * UU + j]   = (lt[i] - m2) * r2 * g2[j] + b2[j];
    }
}

// ---------------------------------------------------------------------------
// Mini 8-head attention. One CTA per batch row; reduces 32 qkv partials.
// ---------------------------------------------------------------------------
__device__ __noinline__ void attn(int b)
{
    __shared__ float q[1024], k[1024], v[1024], sc[64];
    const int t = threadIdx.x;

    for (int j = t; j < 3072; j += 256) {
        int base = b * 3072 + j;
        float s = 0.f;
#pragma unroll
        for (int sp = 0; sp < 32; sp++) s += g_qkvp[sp][base];
        if (j < 1024)       q[j] = s;
        else if (j < 2048)  k[j - 1024] = s;
        else                v[j - 2048] = s;
    }
    __syncthreads();

    if (t < 64) {
        int h = t >> 3, g = t & 7;
        float s = 0.f;
#pragma unroll 8
        for (int d = 0; d < 128; d++) s += q[h * 128 + d] * k[g * 128 + d];
        sc[t] = s * 0.08838834764831845f;   // 1/sqrt(128)
    }
    __syncthreads();

    if (t < 8) {
        float mx = -1e30f;
#pragma unroll
        for (int g = 0; g < 8; g++) mx = fmaxf(mx, sc[t * 8 + g]);
        float e[8], sum = 0.f;
#pragma unroll
        for (int g = 0; g < 8; g++) { e[g] = expf(sc[t * 8 + g] - mx); sum += e[g]; }
        float is = 1.0f / sum;
#pragma unroll
        for (int g = 0; g < 8; g++) sc[t * 8 + g] = e[g] * is;
    }
    __syncthreads();

    for (int j = t; j < 1024; j += 256) {
        int h = j >> 7, d = j & 127;
        float a = 0.f;
#pragma unroll
        for (int g = 0; g < 8; g++) a += sc[h * 8 + g] * v[g * 128 + d];
        g_att[b * UU + j] = a;
    }
}

// ---------------------------------------------------------------------------
// The single persistent kernel.
// ---------------------------------------------------------------------------
__global__ void __launch_bounds__(256, 1) persist(
    const float* __restrict__ x,  const float* __restrict__ kx, const float* __restrict__ kh,
    const float* __restrict__ Wq, const float* __restrict__ Wk, const float* __restrict__ Wv,
    const float* __restrict__ Wo, const float* __restrict__ Wf, const float* __restrict__ Wi,
    const float* __restrict__ g1, const float* __restrict__ b1,
    const float* __restrict__ g2, const float* __restrict__ b2,
    float* __restrict__ y)
{
    unsigned phase = g_release;                       // carries across launches
    const int tid = threadIdx.x;
    const int gt  = blockIdx.x * 256 + tid;           // 0..32767

    // phase 0: pack fused weights, zero carry
    for (int i = gt; i < UU * 2048; i += NB * 256) {
        int kk = i >> 11, j = i & 2047;
        g_Wfi[i] = (j < 1024) ? Wf[(kk << 10) + j] : Wi[(kk << 10) + j - 1024];
    }
    for (int i = gt; i < UU * 3072; i += NB * 256) {
        int kk = i / 3072, j = i - kk * 3072;
        float vv = (j < 1024) ? Wq[kk * 1024 + j]
                 : (j < 2048) ? Wk[kk * 1024 + j - 1024]
                              : Wv[kk * 1024 + j - 2048];
        g_Wqkv[i] = vv;
    }
    for (int i = gt; i < BB * UU; i += NB * 256) g_c[i] = 0.f;
    gsync(phase);

    // XP = x @ kernel_x : 256 rowtiles x 4 coltiles (K = 512 full)
    for (int u = blockIdx.x; u < 1024; u += NB) {
        int rt = u >> 2, ct = u & 3;
        gemm_tile(x + (size_t)rt * 64 * FF, FF, kx, UU,
                  g_XP + (size_t)rt * 64 * UU, UU, ct * 256, 0, FF);
    }
    gsync(phase);

    for (int t = 0; t < TT; t++) {
        const float* h = (t == 0) ? g_zero : (y + (size_t)(t - 1) * UU);
        const int ldh  = (t == 0) ? UU : (TT * UU);

        // ph1: xx partials = h @ kernel_h  (4 coltiles x 32 ksplits of 32)
        for (int u = blockIdx.x; u < 128; u += NB) {
            int ks = u >> 2, ct = u & 3;
            gemm_tile(h, ldh, kh, UU, g_xxp[ks], UU, ct * 256, ks * 32, 32);
        }
        gsync(phase);

        // ph2: xx = XP[:,t,:] + sum of 32 partials
        for (int i = gt; i < BB * UU; i += NB * 256) {
            int b = i >> 10, uu = i & 1023;
            float s = g_XP[(size_t)((b << 8) + t) * UU + uu];
#pragma unroll
            for (int sp = 0; sp < 32; sp++) s += g_xxp[sp][i];
            g_xx[i] = s;
        }
        gsync(phase);

        // ph3: [f|i] partials = xx @ Wfi  (8 coltiles x 16 ksplits of 64)
        for (int u = blockIdx.x; u < 128; u += NB) {
            int ks = u >> 3, ct = u & 7;
            gemm_tile(g_xx, UU, g_Wfi, 2048, g_fip[ks], 2048, ct * 256, ks * 64, 64);
        }
        gsync(phase);

        // ph4: gates + swish + both LayerNorms
        if (blockIdx.x < 64) fi_epi(blockIdx.x, g1, b1, g2, b2);
        gsync(phase);

        // ph5: [q|k|v] partials = st1 @ Wqkv  (12 coltiles x 32 ksplits of 32)
        for (int u = blockIdx.x; u < 384; u += NB) {
            int ks = u / 12, ct = u - ks * 12;
            gemm_tile(g_st1, UU, g_Wqkv, 3072, g_qkvp[ks], 3072, ct * 256, ks * 32, 32);
        }
        gsync(phase);

        // ph6: attention
        if (blockIdx.x < 64) attn(blockIdx.x);
        gsync(phase);

        // ph7: out partials = attended @ W_o  (4 coltiles x 32 ksplits of 32)
        for (int u = blockIdx.x; u < 128; u += NB) {
            int ks = u >> 2, ct = u & 3;
            gemm_tile(g_att, UU, Wo, UU, g_outp[ks], UU, ct * 256, ks * 32, 32);
        }
        gsync(phase);

        // ph8: y[:,t,:] = st1 + sum of 32 partials  (= h for t+1)
        for (int i = gt; i < BB * UU; i += NB * 256) {
            int b = i >> 10, uu = i & 1023;
            float s = g_st1[i];
#pragma unroll
            for (int sp = 0; sp < 32; sp++) s += g_outp[sp][i];
            y[(size_t)b * (TT * UU) + (size_t)t * UU + uu] = s;
        }
        gsync(phase);
    }
}

// ---------------------------------------------------------------------------
// Host: ONE launch -> one graph node.
// ---------------------------------------------------------------------------
extern "C" void kernel_launch(void* const* d_in, const int* in_sizes, int n_in,
                              void* d_out, int out_size)
{
    (void)in_sizes; (void)n_in; (void)out_size;
    persist<<<NB, 256>>>(
        (const float*)d_in[0],  (const float*)d_in[1],  (const float*)d_in[2],
        (const float*)d_in[3],  (const float*)d_in[4],  (const float*)d_in[5],
        (const float*)d_in[6],  (const float*)d_in[7],  (const float*)d_in[8],
        (const float*)d_in[9],  (const float*)d_in[10],
        (const float*)d_in[11], (const float*)d_in[12],
        (float*)d_out);
}